// round 4
// baseline (speedup 1.0000x reference)
#include <cuda_runtime.h>

#define Z 16  // batch chunks of 16

// Scratch: partial batch-sums of x [z][i][c] and the batch-summed u_hat.
__device__ float g_part[Z * 8 * 1152];        // 590 KB
__device__ float g_us[1152 * 160];            // 737 KB

// Kernel A: g_part[z][i][c] = sum over 16 batches of chunk z of x[b,i,c].
// x: [256, 8, 1152] f32 viewed as [256, 2304] float4 rows.
__global__ void __launch_bounds__(256) reduce_x_kernel(const float* __restrict__ x) {
    const int col = blockIdx.x * 256 + threadIdx.x;  // 0..2303 float4 columns
    const int z = blockIdx.y;                        // 0..15
    const float4* p = reinterpret_cast<const float4*>(x) + (size_t)z * 16 * 2304 + col;
    float4 a = make_float4(0.f, 0.f, 0.f, 0.f);
    #pragma unroll
    for (int b = 0; b < 16; ++b) {
        const float4 v = p[(size_t)b * 2304];
        a.x += v.x; a.y += v.y; a.z += v.z; a.w += v.w;
    }
    reinterpret_cast<float4*>(g_part)[(size_t)z * 2304 + col] = a;
}

// Kernel B: pure streaming GEMV. us[c,u,s] = sum_i W[c,u,s,i] * xs[i][c].
// One 160-thread block per capsule; no routing, minimal critical path so
// block turnover keeps the W stream saturating DRAM.
__global__ void __launch_bounds__(160) us_kernel(const float* __restrict__ W) {
    const int c = blockIdx.x;
    const int t = threadIdx.x;

    __shared__ float xs[8];

    const float4* wp = reinterpret_cast<const float4*>(W + (size_t)c * 1280) + 2 * t;
    const float4 w0 = __ldg(wp);
    const float4 w1 = __ldg(wp + 1);

    if (t < 8) {
        float a = 0.f;
        #pragma unroll
        for (int z = 0; z < Z; ++z)
            a += g_part[(z * 8 + t) * 1152 + c];
        xs[t] = a;
    }
    __syncthreads();

    g_us[(size_t)c * 160 + t] =
          w0.x * xs[0] + w0.y * xs[1] + w0.z * xs[2] + w0.w * xs[3]
        + w1.x * xs[4] + w1.y * xs[5] + w1.z * xs[6] + w1.w * xs[7];
}

// Kernel C: routing, one WARP per capsule, zero barriers / zero smem.
// Lane owns 5 (u,s): t = k*32+lane, u = 2k + (lane>>4), s = lane&15.
__global__ void __launch_bounds__(256) routing_kernel(float* __restrict__ out) {
    const int warp = threadIdx.x >> 5;
    const int lane = threadIdx.x & 31;
    const int c = blockIdx.x * 8 + warp;     // 144 * 8 = 1152
    const int h = lane >> 4;                 // u parity

    float us[5];
    #pragma unroll
    for (int k = 0; k < 5; ++k)
        us[k] = g_us[(size_t)c * 160 + k * 32 + lane];  // coalesced L2 hits

    float be[5] = {0.f, 0.f, 0.f, 0.f, 0.f};  // logits, u = 2k
    float bo[5] = {0.f, 0.f, 0.f, 0.f, 0.f};  // logits, u = 2k+1
    float cij[5] = {0.1f, 0.1f, 0.1f, 0.1f, 0.1f};  // softmax(0) = 1/10 exactly
    float v[5];

    #pragma unroll
    for (int it = 0; it < 3; ++it) {
        #pragma unroll
        for (int k = 0; k < 5; ++k) {
            const float sj = cij[k] * us[k];

            float msq = sj * sj;                 // ||s_j||^2 over 16 s-lanes
            #pragma unroll
            for (int off = 8; off; off >>= 1)
                msq += __shfl_xor_sync(0xffffffffu, msq, off);

            v[k] = msq / (1.0f + msq) * sj * rsqrtf(msq);

            if (it < 2) {
                float a = us[k] * v[k];          // agreement over s
                #pragma unroll
                for (int off = 8; off; off >>= 1)
                    a += __shfl_xor_sync(0xffffffffu, a, off);
                a *= (1.0f / 256.0f);
                const float ap = __shfl_xor_sync(0xffffffffu, a, 16);
                be[k] += h ? ap : a;
                bo[k] += h ? a : ap;
            }
        }

        if (it < 2) {
            // softmax over the 10 u's, fully in registers (each lane holds all)
            float m = be[0];
            #pragma unroll
            for (int k = 0; k < 5; ++k) { m = fmaxf(m, be[k]); m = fmaxf(m, bo[k]); }
            float ee[5], eo[5], denom = 0.f;
            #pragma unroll
            for (int k = 0; k < 5; ++k) {
                ee[k] = __expf(be[k] - m);
                eo[k] = __expf(bo[k] - m);
                denom += ee[k] + eo[k];
            }
            const float inv = 1.0f / denom;
            #pragma unroll
            for (int k = 0; k < 5; ++k)
                cij[k] = (h ? eo[k] : ee[k]) * inv;
        }
    }

    #pragma unroll
    for (int k = 0; k < 5; ++k)
        out[(size_t)c * 160 + k * 32 + lane] = v[k];
}

extern "C" void kernel_launch(void* const* d_in, const int* in_sizes, int n_in,
                              void* d_out, int out_size) {
    const float* x = (const float*)d_in[0];   // [256, 8, 1152]
    const float* W = (const float*)d_in[1];   // [1, 1152, 10, 16, 8]
    float* out = (float*)d_out;               // [1152, 10, 16]

    reduce_x_kernel<<<dim3(9, Z), 256>>>(x);
    us_kernel<<<1152, 160>>>(W);
    routing_kernel<<<144, 256>>>(out);
}